// round 8
// baseline (speedup 1.0000x reference)
#include <cuda_runtime.h>
#include <math.h>
#include <stdint.h>

#define MAX_ATOMS 50000

__device__ float g_dEdD[MAX_ATOMS * 64];

// ---- smem float-offset map ----
// W1s: [d=64][t=128] float2{hi,lo}, row stride 132 f2  (conflict-free banks)
// W2s: [t=128][j=64] float2{hi,lo}, row stride 68 f2
#define O_W1S 0
#define O_W2S 16896              // 64*132*2 floats
#define O_B1  (O_W2S + 17408)    // 128*68*2 floats
#define O_B2  (O_B1 + 128)
#define O_W3  (O_B2 + 64)
#define O_H1  (O_W3 + 64)        // per-warp h1/g1 buffers [16][132]
#define H1W_FLOATS (16 * 132)
#define SMEM_FLOATS (O_H1 + 8 * H1W_FLOATS)   // 51456 floats = 205824 B

// m16n8k8 tf32 mma, fp32 accumulate, D==C in place
__device__ __forceinline__ void mma8(float* d,
                                     uint32_t a0, uint32_t a1, uint32_t a2, uint32_t a3,
                                     uint32_t b0, uint32_t b1) {
    asm("mma.sync.aligned.m16n8k8.row.col.f32.tf32.tf32.f32 "
        "{%0,%1,%2,%3}, {%4,%5,%6,%7}, {%8,%9}, {%0,%1,%2,%3};"
        : "+f"(d[0]), "+f"(d[1]), "+f"(d[2]), "+f"(d[3])
        : "r"(a0), "r"(a1), "r"(a2), "r"(a3), "r"(b0), "r"(b1));
}
// error-compensated tf32 split: v = hi + lo (+ O(2^-22))
__device__ __forceinline__ void split_tf32(float v, uint32_t& hi, uint32_t& lo) {
    uint32_t h;
    asm("cvt.rna.tf32.f32 %0, %1;" : "=r"(h) : "f"(v));
    float r = v - __uint_as_float(h);
    asm("cvt.rna.tf32.f32 %0, %1;" : "=r"(lo) : "f"(r));
    hi = h;
}

// ---------------------------------------------------------------------------
// MLP fwd+bwd on tensor cores. 256 thr = 8 autonomous warps; 16 atoms/warp
// per chunk, grid-stride. Four GEMMs per chunk via m16n8k8 tf32 with
// hi/lo error compensation (3 mma per k-tile). Weight strides 132/68 f2 give
// conflict-free half-warp LDS.64 banks for all four B access patterns.
// ---------------------------------------------------------------------------
__global__ void __launch_bounds__(256, 1)
mlp_kernel(const float* __restrict__ x, const int* __restrict__ indices,
           const float* __restrict__ W1, const float* __restrict__ b1,
           const float* __restrict__ W2, const float* __restrict__ b2,
           const float* __restrict__ W3, const float* __restrict__ b3,
           float* __restrict__ energy, int natoms)
{
    extern __shared__ float sm[];
    float2* W1s = (float2*)(sm + O_W1S);
    float2* W2s = (float2*)(sm + O_W2S);
    const int tid  = threadIdx.x;
    const int wid  = tid >> 5;
    const int lane = tid & 31;

    // ---- stage weights as {tf32-hi, tf32-lo} float2 ----
    for (int i = tid; i < 64 * 128; i += 256) {       // W1 [d][t]
        int d = i >> 7, t = i & 127;
        uint32_t hi, lo; split_tf32(W1[i], hi, lo);
        W1s[d * 132 + t] = make_float2(__uint_as_float(hi), __uint_as_float(lo));
    }
    for (int i = tid; i < 128 * 64; i += 256) {       // W2 [t][j]
        int t = i >> 6, j = i & 63;
        uint32_t hi, lo; split_tf32(W2[i], hi, lo);
        W2s[t * 68 + j] = make_float2(__uint_as_float(hi), __uint_as_float(lo));
    }
    if (tid < 128) sm[O_B1 + tid] = b1[tid];
    if (tid < 64)  { sm[O_B2 + tid] = b2[tid]; sm[O_W3 + tid] = W3[tid]; }
    const float b3v = b3[0];
    __syncthreads();

    float* h1s = sm + O_H1 + wid * H1W_FLOATS;    // [16][132], h1 then g1
    const int g = lane >> 2;     // groupID 0..7
    const int t = lane & 3;      // threadID in group
    const bool odd = t & 1;

    const int gwarp  = blockIdx.x * 8 + wid;
    const int nwarps = gridDim.x * 8;
    const int nchunk = (natoms + 15) >> 4;

    for (int chunk = gwarp; chunk < nchunk; chunk += nwarps) {
        const int base = chunk << 4;
        const int r0 = base + g, r1 = base + g + 8;
        const bool ok0 = r0 < natoms, ok1 = r1 < natoms;

        // ================= GEMM1: H1pre = X @ W1 (N=128, K=64) ============
        float acc[16][4];
        #pragma unroll
        for (int nt = 0; nt < 16; nt++)
            #pragma unroll
            for (int q = 0; q < 4; q++) acc[nt][q] = 0.f;

        #pragma unroll 1
        for (int s = 0; s < 8; s++) {
            int c = 8 * s + t;
            float ar0 = ok0 ? __ldg(x + (size_t)r0 * 64 + c)     : 0.f;
            float ar1 = ok1 ? __ldg(x + (size_t)r1 * 64 + c)     : 0.f;
            float ar2 = ok0 ? __ldg(x + (size_t)r0 * 64 + c + 4) : 0.f;
            float ar3 = ok1 ? __ldg(x + (size_t)r1 * 64 + c + 4) : 0.f;
            uint32_t ah0, al0, ah1, al1, ah2, al2, ah3, al3;
            split_tf32(ar0, ah0, al0); split_tf32(ar1, ah1, al1);
            split_tf32(ar2, ah2, al2); split_tf32(ar3, ah3, al3);
            const float2* wr0 = W1s + (8 * s + t) * 132;
            const float2* wr1 = W1s + (8 * s + t + 4) * 132;
            #pragma unroll
            for (int nt = 0; nt < 16; nt++) {
                float2 w0 = wr0[8 * nt + g];
                float2 w1 = wr1[8 * nt + g];
                uint32_t b0h = __float_as_uint(w0.x), b1h = __float_as_uint(w1.x);
                uint32_t b0l = __float_as_uint(w0.y), b1l = __float_as_uint(w1.y);
                mma8(acc[nt], ah0, ah1, ah2, ah3, b0h, b1h);
                mma8(acc[nt], al0, al1, al2, al3, b0h, b1h);
                mma8(acc[nt], ah0, ah1, ah2, ah3, b0l, b1l);
            }
        }
        // epi1: h1 = tanh(. + b1) -> h1s
        #pragma unroll
        for (int nt = 0; nt < 16; nt++) {
            int c = 8 * nt + 2 * t;
            float2 bb = *(const float2*)(sm + O_B1 + c);
            float2 v0 = make_float2(tanhf(acc[nt][0] + bb.x), tanhf(acc[nt][1] + bb.y));
            float2 v1 = make_float2(tanhf(acc[nt][2] + bb.x), tanhf(acc[nt][3] + bb.y));
            *(float2*)(h1s + g * 132 + c)       = v0;
            *(float2*)(h1s + (g + 8) * 132 + c) = v1;
        }
        __syncwarp();

        // ================= GEMM2: H2pre = H1 @ W2 (N=64, K=128) ===========
        float ac2[8][4];
        #pragma unroll
        for (int nt = 0; nt < 8; nt++)
            #pragma unroll
            for (int q = 0; q < 4; q++) ac2[nt][q] = 0.f;

        #pragma unroll 1
        for (int s = 0; s < 16; s++) {
            int c = 8 * s + t;
            float ar0 = h1s[g * 132 + c];
            float ar1 = h1s[(g + 8) * 132 + c];
            float ar2 = h1s[g * 132 + c + 4];
            float ar3 = h1s[(g + 8) * 132 + c + 4];
            uint32_t ah0, al0, ah1, al1, ah2, al2, ah3, al3;
            split_tf32(ar0, ah0, al0); split_tf32(ar1, ah1, al1);
            split_tf32(ar2, ah2, al2); split_tf32(ar3, ah3, al3);
            const float2* wr0 = W2s + (8 * s + t) * 68;
            const float2* wr1 = W2s + (8 * s + t + 4) * 68;
            #pragma unroll
            for (int nt = 0; nt < 8; nt++) {
                float2 w0 = wr0[8 * nt + g];
                float2 w1 = wr1[8 * nt + g];
                uint32_t b0h = __float_as_uint(w0.x), b1h = __float_as_uint(w1.x);
                uint32_t b0l = __float_as_uint(w0.y), b1l = __float_as_uint(w1.y);
                mma8(ac2[nt], ah0, ah1, ah2, ah3, b0h, b1h);
                mma8(ac2[nt], al0, al1, al2, al3, b0h, b1h);
                mma8(ac2[nt], ah0, ah1, ah2, ah3, b0l, b1l);
            }
        }
        // epi2: h2 = tanh(.+b2); energy; d2 = w3*(1-h2^2) kept in regs
        float d2v[8][4];
        float e0 = 0.f, e1 = 0.f;
        #pragma unroll
        for (int nt = 0; nt < 8; nt++) {
            int c = 8 * nt + 2 * t;
            float2 bb = *(const float2*)(sm + O_B2 + c);
            float2 w3 = *(const float2*)(sm + O_W3 + c);
            float h0 = tanhf(ac2[nt][0] + bb.x);
            float h1v = tanhf(ac2[nt][1] + bb.y);
            float h2v = tanhf(ac2[nt][2] + bb.x);
            float h3v = tanhf(ac2[nt][3] + bb.y);
            e0 += h0 * w3.x + h1v * w3.y;
            e1 += h2v * w3.x + h3v * w3.y;
            d2v[nt][0] = w3.x * (1.f - h0 * h0);
            d2v[nt][1] = w3.y * (1.f - h1v * h1v);
            d2v[nt][2] = w3.x * (1.f - h2v * h2v);
            d2v[nt][3] = w3.y * (1.f - h3v * h3v);
        }
        e0 += __shfl_xor_sync(0xffffffffu, e0, 1);
        e0 += __shfl_xor_sync(0xffffffffu, e0, 2);
        e1 += __shfl_xor_sync(0xffffffffu, e1, 1);
        e1 += __shfl_xor_sync(0xffffffffu, e1, 2);
        if (t == 0) {
            if (ok0) atomicAdd(&energy[__ldg(indices + r0)], e0 + b3v);
            if (ok1) atomicAdd(&energy[__ldg(indices + r1)], e1 + b3v);
        }

        // ============ GEMM3: G1pre = D2 @ W2^T (N=128, K=64) ==============
        float ac3[16][4];
        #pragma unroll
        for (int nt = 0; nt < 16; nt++)
            #pragma unroll
            for (int q = 0; q < 4; q++) ac3[nt][q] = 0.f;

        #pragma unroll 1
        for (int s = 0; s < 8; s++) {
            int srcA = 4 * g + (t >> 1);
            int srcB = srcA + 2;
            float q0 = __shfl_sync(0xffffffffu, d2v[s][0], srcA);
            float q1 = __shfl_sync(0xffffffffu, d2v[s][1], srcA);
            float q2 = __shfl_sync(0xffffffffu, d2v[s][2], srcA);
            float q3 = __shfl_sync(0xffffffffu, d2v[s][3], srcA);
            float p0 = __shfl_sync(0xffffffffu, d2v[s][0], srcB);
            float p1 = __shfl_sync(0xffffffffu, d2v[s][1], srcB);
            float p2 = __shfl_sync(0xffffffffu, d2v[s][2], srcB);
            float p3 = __shfl_sync(0xffffffffu, d2v[s][3], srcB);
            float ar0 = odd ? q1 : q0;
            float ar1 = odd ? q3 : q2;
            float ar2 = odd ? p1 : p0;
            float ar3 = odd ? p3 : p2;
            uint32_t ah0, al0, ah1, al1, ah2, al2, ah3, al3;
            split_tf32(ar0, ah0, al0); split_tf32(ar1, ah1, al1);
            split_tf32(ar2, ah2, al2); split_tf32(ar3, ah3, al3);
            #pragma unroll
            for (int nt = 0; nt < 16; nt++) {
                float2 w0 = W2s[(8 * nt + g) * 68 + 8 * s + t];
                float2 w1 = W2s[(8 * nt + g) * 68 + 8 * s + t + 4];
                uint32_t b0h = __float_as_uint(w0.x), b1h = __float_as_uint(w1.x);
                uint32_t b0l = __float_as_uint(w0.y), b1l = __float_as_uint(w1.y);
                mma8(ac3[nt], ah0, ah1, ah2, ah3, b0h, b1h);
                mma8(ac3[nt], al0, al1, al2, al3, b0h, b1h);
                mma8(ac3[nt], ah0, ah1, ah2, ah3, b0l, b1l);
            }
        }
        // epi3: g1 = G1pre * (1 - h1^2), in place over h1s
        #pragma unroll
        for (int nt = 0; nt < 16; nt++) {
            int c = 8 * nt + 2 * t;
            float2* ptr0 = (float2*)(h1s + g * 132 + c);
            float2* ptr1 = (float2*)(h1s + (g + 8) * 132 + c);
            float2 h0 = *ptr0, h1v = *ptr1;
            *ptr0 = make_float2(ac3[nt][0] * (1.f - h0.x * h0.x),
                                ac3[nt][1] * (1.f - h0.y * h0.y));
            *ptr1 = make_float2(ac3[nt][2] * (1.f - h1v.x * h1v.x),
                                ac3[nt][3] * (1.f - h1v.y * h1v.y));
        }
        __syncwarp();

        // ============ GEMM4: dEdD = G1 @ W1^T (N=64, K=128) ===============
        float ac4[8][4];
        #pragma unroll
        for (int nt = 0; nt < 8; nt++)
            #pragma unroll
            for (int q = 0; q < 4; q++) ac4[nt][q] = 0.f;

        #pragma unroll 1
        for (int s = 0; s < 16; s++) {
            int c = 8 * s + t;
            float ar0 = h1s[g * 132 + c];
            float ar1 = h1s[(g + 8) * 132 + c];
            float ar2 = h1s[g * 132 + c + 4];
            float ar3 = h1s[(g + 8) * 132 + c + 4];
            uint32_t ah0, al0, ah1, al1, ah2, al2, ah3, al3;
            split_tf32(ar0, ah0, al0); split_tf32(ar1, ah1, al1);
            split_tf32(ar2, ah2, al2); split_tf32(ar3, ah3, al3);
            #pragma unroll
            for (int nt = 0; nt < 8; nt++) {
                float2 w0 = W1s[(8 * nt + g) * 132 + 8 * s + t];
                float2 w1 = W1s[(8 * nt + g) * 132 + 8 * s + t + 4];
                uint32_t b0h = __float_as_uint(w0.x), b1h = __float_as_uint(w1.x);
                uint32_t b0l = __float_as_uint(w0.y), b1l = __float_as_uint(w1.y);
                mma8(ac4[nt], ah0, ah1, ah2, ah3, b0h, b1h);
                mma8(ac4[nt], al0, al1, al2, al3, b0h, b1h);
                mma8(ac4[nt], ah0, ah1, ah2, ah3, b0l, b1l);
            }
        }
        // epi4: store dEdD
        #pragma unroll
        for (int nt = 0; nt < 8; nt++) {
            int c = 8 * nt + 2 * t;
            if (ok0)
                *(float2*)(g_dEdD + (size_t)r0 * 64 + c)
                    = make_float2(ac4[nt][0], ac4[nt][1]);
            if (ok1)
                *(float2*)(g_dEdD + (size_t)r1 * 64 + c)
                    = make_float2(ac4[nt][2], ac4[nt][3]);
        }
        __syncwarp();
    }
}

// ---------------------------------------------------------------------------
// Forces: 8 pairs per warp, 4-lane groups, 16 LDG.128 in flight per lane.
// ---------------------------------------------------------------------------
__global__ void __launch_bounds__(256)
forces_kernel(const float* __restrict__ xd, const int* __restrict__ xd_indx,
              const int* __restrict__ uj, float* __restrict__ forces, int npairs)
{
    int w    = (blockIdx.x * blockDim.x + threadIdx.x) >> 5;
    int lane = threadIdx.x & 31;
    int li   = lane & 3;
    int pr   = lane >> 2;
    int p    = 8 * w + pr;
    if (8 * w >= npairs) return;
    bool valid = (p < npairs);
    int pc = valid ? p : (npairs - 1);

    int neigh = __ldg(xd_indx + 6 * pc);
    const float4* gp = (const float4*)(g_dEdD + (size_t)neigh * 64) + 4 * li;
    float4 g0 = __ldg(gp), g1 = __ldg(gp + 1), g2 = __ldg(gp + 2), g3 = __ldg(gp + 3);

    const float4* xr = (const float4*)(xd + (size_t)pc * 192) + 4 * li;
    float4 a0 = __ldcs(xr + 0),  a1 = __ldcs(xr + 1);
    float4 a2 = __ldcs(xr + 2),  a3 = __ldcs(xr + 3);
    float4 b0 = __ldcs(xr + 16), b1 = __ldcs(xr + 17);
    float4 b2 = __ldcs(xr + 18), b3 = __ldcs(xr + 19);
    float4 c0 = __ldcs(xr + 32), c1 = __ldcs(xr + 33);
    float4 c2 = __ldcs(xr + 34), c3 = __ldcs(xr + 35);

    float s0 = a0.x*g0.x + a0.y*g0.y + a0.z*g0.z + a0.w*g0.w
             + a1.x*g1.x + a1.y*g1.y + a1.z*g1.z + a1.w*g1.w
             + a2.x*g2.x + a2.y*g2.y + a2.z*g2.z + a2.w*g2.w
             + a3.x*g3.x + a3.y*g3.y + a3.z*g3.z + a3.w*g3.w;
    float s1 = b0.x*g0.x + b0.y*g0.y + b0.z*g0.z + b0.w*g0.w
             + b1.x*g1.x + b1.y*g1.y + b1.z*g1.z + b1.w*g1.w
             + b2.x*g2.x + b2.y*g2.y + b2.z*g2.z + b2.w*g2.w
             + b3.x*g3.x + b3.y*g3.y + b3.z*g3.z + b3.w*g3.w;
    float s2 = c0.x*g0.x + c0.y*g0.y + c0.z*g0.z + c0.w*g0.w
             + c1.x*g1.x + c1.y*g1.y + c1.z*g1.z + c1.w*g1.w
             + c2.x*g2.x + c2.y*g2.y + c2.z*g2.z + c2.w*g2.w
             + c3.x*g3.x + c3.y*g3.y + c3.z*g3.z + c3.w*g3.w;

    #pragma unroll
    for (int off = 2; off; off >>= 1) {
        s0 += __shfl_xor_sync(0xffffffffu, s0, off);
        s1 += __shfl_xor_sync(0xffffffffu, s1, off);
        s2 += __shfl_xor_sync(0xffffffffu, s2, off);
    }
    if (li == 0 && valid) {
        int j0 = __ldg(uj + 3 * pc);
        int j1 = __ldg(uj + 3 * pc + 1);
        int j2 = __ldg(uj + 3 * pc + 2);
        atomicAdd(&forces[3 * j0 + 0], -s0);
        atomicAdd(&forces[3 * j1 + 1], -s1);
        atomicAdd(&forces[3 * j2 + 2], -s2);
    }
}

// ---------------------------------------------------------------------------
extern "C" void kernel_launch(void* const* d_in, const int* in_sizes, int n_in,
                              void* d_out, int out_size)
{
    const float* x       = (const float*)d_in[0];
    const float* xd      = (const float*)d_in[1];
    const int*   indices = (const int*)  d_in[2];
    const int*   xd_indx = (const int*)  d_in[4];
    const int*   uj      = (const int*)  d_in[5];
    const float* W1      = (const float*)d_in[6];
    const float* b1      = (const float*)d_in[7];
    const float* W2      = (const float*)d_in[8];
    const float* b2      = (const float*)d_in[9];
    const float* W3      = (const float*)d_in[10];
    const float* b3      = (const float*)d_in[11];
    float* out = (float*)d_out;

    int natoms  = in_sizes[0] / 64;    // 50000
    int nstruct = in_sizes[3];         // 250
    int npairs  = in_sizes[5] / 3;     // 1000000

    cudaMemsetAsync(out, 0, (size_t)out_size * sizeof(float), 0);

    const int smem_bytes = SMEM_FLOATS * (int)sizeof(float);   // 205,824 B
    cudaFuncSetAttribute(mlp_kernel, cudaFuncAttributeMaxDynamicSharedMemorySize,
                         smem_bytes);
    mlp_kernel<<<148, 256, smem_bytes>>>(x, indices, W1, b1, W2, b2, W3, b3,
                                         out, natoms);

    int nwarps = (npairs + 7) / 8;
    int blocks = (nwarps + 7) / 8;
    forces_kernel<<<blocks, 256>>>(xd, xd_indx, uj, out + nstruct, npairs);
}

// round 9
// speedup vs baseline: 1.7547x; 1.7547x over previous
#include <cuda_runtime.h>
#include <math.h>
#include <stdint.h>

#define MAX_ATOMS 50000

__device__ float g_dEdD[MAX_ATOMS * 64];

// ---- smem byte-offset map (~214 KB) ----
// All weight arrays are uint2 {bf16x2_hi, bf16x2_lo} per consecutive-k pair.
// Row strides (in uint2): 36 or 68 -> row step = 8 words (mod 32): conflict-free.
#define OB_W1B  0         // [t=128][dpair<32]  stride 36 : B of GEMM1
#define OB_W2B  36864     // [j=64][tpair<64]   stride 68 : B of GEMM2
#define OB_W2TB 71680     // [t=128][jpair<32]  stride 36 : B of GEMM3
#define OB_W1TB 108544    // [d=64][tpair<64]   stride 68 : B of GEMM4
#define OB_B1   143360
#define OB_B2   143872
#define OB_W3   144128
#define OB_H1   144384    // per-warp h1/g1: [16 rows][tpair<64] stride 68 uint2
#define H1W_BYTES (16 * 68 * 8)     // 8704
#define SMEM_BYTES (OB_H1 + 8 * H1W_BYTES)   // 214016

// m16n8k16 bf16 mma, fp32 accumulate, D==C in place
__device__ __forceinline__ void mma16(float* d,
                                      uint32_t a0, uint32_t a1, uint32_t a2, uint32_t a3,
                                      uint32_t b0, uint32_t b1) {
    asm("mma.sync.aligned.m16n8k16.row.col.f32.bf16.bf16.f32 "
        "{%0,%1,%2,%3}, {%4,%5,%6,%7}, {%8,%9}, {%0,%1,%2,%3};"
        : "+f"(d[0]), "+f"(d[1]), "+f"(d[2]), "+f"(d[3])
        : "r"(a0), "r"(a1), "r"(a2), "r"(a3), "r"(b0), "r"(b1));
}
// split pair (v0=k, v1=k+1) into bf16x2 hi pack + bf16x2 lo pack.
// v = hi + lo with |err| ~ 2^-18 |v|.
__device__ __forceinline__ void split_pair(float v0, float v1,
                                           uint32_t& hi, uint32_t& lo) {
    uint32_t h;
    asm("cvt.rn.bf16x2.f32 %0, %1, %2;" : "=r"(h) : "f"(v1), "f"(v0));
    float h0 = __uint_as_float(h << 16);
    float h1 = __uint_as_float(h & 0xffff0000u);
    asm("cvt.rn.bf16x2.f32 %0, %1, %2;" : "=r"(lo) : "f"(v1 - h1), "f"(v0 - h0));
    hi = h;
}
__device__ __forceinline__ float bf_lo(uint32_t p) { return __uint_as_float(p << 16); }
__device__ __forceinline__ float bf_hi(uint32_t p) { return __uint_as_float(p & 0xffff0000u); }

// ---------------------------------------------------------------------------
// MLP fwd+bwd on bf16 tensor cores with 3-mma error compensation.
// 256 thr = 8 autonomous warps; 16 atoms/warp/chunk, grid-stride.
// ---------------------------------------------------------------------------
__global__ void __launch_bounds__(256, 1)
mlp_kernel(const float* __restrict__ x, const int* __restrict__ indices,
           const float* __restrict__ W1, const float* __restrict__ b1,
           const float* __restrict__ W2, const float* __restrict__ b2,
           const float* __restrict__ W3, const float* __restrict__ b3,
           float* __restrict__ energy, int natoms)
{
    extern __shared__ char smraw[];
    uint2* W1B  = (uint2*)(smraw + OB_W1B);
    uint2* W2B  = (uint2*)(smraw + OB_W2B);
    uint2* W2TB = (uint2*)(smraw + OB_W2TB);
    uint2* W1TB = (uint2*)(smraw + OB_W1TB);
    float* b1s  = (float*)(smraw + OB_B1);
    float* b2s  = (float*)(smraw + OB_B2);
    float* w3s  = (float*)(smraw + OB_W3);

    const int tid  = threadIdx.x;
    const int wid  = tid >> 5;
    const int lane = tid & 31;

    // ---- stage weights: split into {hi,lo} bf16x2 packs, 4 layouts ----
    for (int i = tid; i < 128 * 32; i += 256) {       // W1B [t][dpair]
        int t = i >> 5, dp = i & 31;
        uint32_t hi, lo;
        split_pair(W1[(2 * dp) * 128 + t], W1[(2 * dp + 1) * 128 + t], hi, lo);
        W1B[t * 36 + dp] = make_uint2(hi, lo);
    }
    for (int i = tid; i < 64 * 64; i += 256) {        // W2B [j][tpair]
        int j = i >> 6, tp = i & 63;
        uint32_t hi, lo;
        split_pair(W2[(2 * tp) * 64 + j], W2[(2 * tp + 1) * 64 + j], hi, lo);
        W2B[j * 68 + tp] = make_uint2(hi, lo);
    }
    for (int i = tid; i < 128 * 32; i += 256) {       // W2TB [t][jpair]
        int t = i >> 5, jp = i & 31;
        uint32_t hi, lo;
        split_pair(W2[t * 64 + 2 * jp], W2[t * 64 + 2 * jp + 1], hi, lo);
        W2TB[t * 36 + jp] = make_uint2(hi, lo);
    }
    for (int i = tid; i < 64 * 64; i += 256) {        // W1TB [d][tpair]
        int d = i >> 6, tp = i & 63;
        uint32_t hi, lo;
        split_pair(W1[d * 128 + 2 * tp], W1[d * 128 + 2 * tp + 1], hi, lo);
        W1TB[d * 68 + tp] = make_uint2(hi, lo);
    }
    if (tid < 128) b1s[tid] = b1[tid];
    if (tid < 64)  { b2s[tid] = b2[tid]; w3s[tid] = W3[tid]; }
    const float b3v = b3[0];
    __syncthreads();

    uint2* h1p = (uint2*)(smraw + OB_H1 + wid * H1W_BYTES);   // [16][stride 68]
    const int g = lane >> 2;     // groupID 0..7
    const int t = lane & 3;      // threadID in group

    const int gwarp  = blockIdx.x * 8 + wid;
    const int nwarps = gridDim.x * 8;
    const int nchunk = (natoms + 15) >> 4;
    const float2* x2 = (const float2*)x;

    for (int chunk = gwarp; chunk < nchunk; chunk += nwarps) {
        const int base = chunk << 4;
        const int r0 = base + g, r1 = base + g + 8;
        const bool ok0 = r0 < natoms, ok1 = r1 < natoms;

        // ========== GEMM1: H1pre = X @ W1  (N=128, K=64: 4 k16-tiles) =====
        float acc[16][4];
        #pragma unroll
        for (int nt = 0; nt < 16; nt++)
            #pragma unroll
            for (int q = 0; q < 4; q++) acc[nt][q] = 0.f;

        #pragma unroll 1
        for (int s = 0; s < 4; s++) {
            float2 z = make_float2(0.f, 0.f);
            float2 v00 = ok0 ? __ldg(x2 + (size_t)r0 * 32 + 8 * s + t)     : z;
            float2 v01 = ok0 ? __ldg(x2 + (size_t)r0 * 32 + 8 * s + t + 4) : z;
            float2 v10 = ok1 ? __ldg(x2 + (size_t)r1 * 32 + 8 * s + t)     : z;
            float2 v11 = ok1 ? __ldg(x2 + (size_t)r1 * 32 + 8 * s + t + 4) : z;
            uint32_t a0h, a0l, a1h, a1l, a2h, a2l, a3h, a3l;
            split_pair(v00.x, v00.y, a0h, a0l);
            split_pair(v10.x, v10.y, a1h, a1l);
            split_pair(v01.x, v01.y, a2h, a2l);
            split_pair(v11.x, v11.y, a3h, a3l);
            #pragma unroll
            for (int nt = 0; nt < 16; nt++) {
                uint2 B0 = W1B[(8 * nt + g) * 36 + 8 * s + t];
                uint2 B1 = W1B[(8 * nt + g) * 36 + 8 * s + t + 4];
                mma16(acc[nt], a0h, a1h, a2h, a3h, B0.x, B1.x);
                mma16(acc[nt], a0l, a1l, a2l, a3l, B0.x, B1.x);
                mma16(acc[nt], a0h, a1h, a2h, a3h, B0.y, B1.y);
            }
        }
        // epi1: h1 = tanh(.+b1) -> h1p as {hi,lo} packs
        #pragma unroll
        for (int nt = 0; nt < 16; nt++) {
            int c = 8 * nt + 2 * t;
            float2 bb = *(const float2*)(b1s + c);
            uint32_t hi, lo;
            split_pair(tanhf(acc[nt][0] + bb.x), tanhf(acc[nt][1] + bb.y), hi, lo);
            h1p[g * 68 + 4 * nt + t] = make_uint2(hi, lo);
            split_pair(tanhf(acc[nt][2] + bb.x), tanhf(acc[nt][3] + bb.y), hi, lo);
            h1p[(g + 8) * 68 + 4 * nt + t] = make_uint2(hi, lo);
        }
        __syncwarp();

        // ========== GEMM2: H2pre = H1 @ W2 (N=64, K=128: 8 k16-tiles) =====
        float ac2[8][4];
        #pragma unroll
        for (int nt = 0; nt < 8; nt++)
            #pragma unroll
            for (int q = 0; q < 4; q++) ac2[nt][q] = 0.f;

        #pragma unroll 1
        for (int s = 0; s < 8; s++) {
            uint2 A00 = h1p[g * 68 + 8 * s + t];
            uint2 A10 = h1p[(g + 8) * 68 + 8 * s + t];
            uint2 A01 = h1p[g * 68 + 8 * s + t + 4];
            uint2 A11 = h1p[(g + 8) * 68 + 8 * s + t + 4];
            #pragma unroll
            for (int nt = 0; nt < 8; nt++) {
                uint2 B0 = W2B[(8 * nt + g) * 68 + 8 * s + t];
                uint2 B1 = W2B[(8 * nt + g) * 68 + 8 * s + t + 4];
                mma16(ac2[nt], A00.x, A10.x, A01.x, A11.x, B0.x, B1.x);
                mma16(ac2[nt], A00.y, A10.y, A01.y, A11.y, B0.x, B1.x);
                mma16(ac2[nt], A00.x, A10.x, A01.x, A11.x, B0.y, B1.y);
            }
        }
        // epi2: h2=tanh(.+b2); energy; d2 = w3*(1-h2^2) kept in regs
        float d2v[8][4];
        float e0 = 0.f, e1 = 0.f;
        #pragma unroll
        for (int nt = 0; nt < 8; nt++) {
            int c = 8 * nt + 2 * t;
            float2 bb = *(const float2*)(b2s + c);
            float2 w3 = *(const float2*)(w3s + c);
            float h0 = tanhf(ac2[nt][0] + bb.x);
            float h1v = tanhf(ac2[nt][1] + bb.y);
            float h2v = tanhf(ac2[nt][2] + bb.x);
            float h3v = tanhf(ac2[nt][3] + bb.y);
            e0 += h0 * w3.x + h1v * w3.y;
            e1 += h2v * w3.x + h3v * w3.y;
            d2v[nt][0] = w3.x * (1.f - h0 * h0);
            d2v[nt][1] = w3.y * (1.f - h1v * h1v);
            d2v[nt][2] = w3.x * (1.f - h2v * h2v);
            d2v[nt][3] = w3.y * (1.f - h3v * h3v);
        }
        e0 += __shfl_xor_sync(0xffffffffu, e0, 1);
        e0 += __shfl_xor_sync(0xffffffffu, e0, 2);
        e1 += __shfl_xor_sync(0xffffffffu, e1, 1);
        e1 += __shfl_xor_sync(0xffffffffu, e1, 2);
        if (t == 0) {
            if (ok0) atomicAdd(&energy[__ldg(indices + r0)], e0 + b3v);
            if (ok1) atomicAdd(&energy[__ldg(indices + r1)], e1 + b3v);
        }

        // ========== GEMM3: G1pre = D2 @ W2^T (N=128, K=64) ================
        // A fragments come straight from d2v (k-pairs == D-frag columns).
        float ac3[16][4];
        #pragma unroll
        for (int nt = 0; nt < 16; nt++)
            #pragma unroll
            for (int q = 0; q < 4; q++) ac3[nt][q] = 0.f;

        #pragma unroll 1
        for (int s = 0; s < 4; s++) {
            uint32_t a0h, a0l, a1h, a1l, a2h, a2l, a3h, a3l;
            split_pair(d2v[2 * s][0],     d2v[2 * s][1],     a0h, a0l);
            split_pair(d2v[2 * s][2],     d2v[2 * s][3],     a1h, a1l);
            split_pair(d2v[2 * s + 1][0], d2v[2 * s + 1][1], a2h, a2l);
            split_pair(d2v[2 * s + 1][2], d2v[2 * s + 1][3], a3h, a3l);
            #pragma unroll
            for (int nt = 0; nt < 16; nt++) {
                uint2 B0 = W2TB[(8 * nt + g) * 36 + 8 * s + t];
                uint2 B1 = W2TB[(8 * nt + g) * 36 + 8 * s + t + 4];
                mma16(ac3[nt], a0h, a1h, a2h, a3h, B0.x, B1.x);
                mma16(ac3[nt], a0l, a1l, a2l, a3l, B0.x, B1.x);
                mma16(ac3[nt], a0h, a1h, a2h, a3h, B0.y, B1.y);
            }
        }
        // epi3: g1 = G1pre * (1 - h1^2), in place over h1p
        #pragma unroll
        for (int nt = 0; nt < 16; nt++) {
            uint2* p0 = h1p + g * 68 + 4 * nt + t;
            uint2* p1 = h1p + (g + 8) * 68 + 4 * nt + t;
            uint2 u0 = *p0, u1 = *p1;
            float h00 = bf_lo(u0.x) + bf_lo(u0.y);
            float h01 = bf_hi(u0.x) + bf_hi(u0.y);
            float h10 = bf_lo(u1.x) + bf_lo(u1.y);
            float h11 = bf_hi(u1.x) + bf_hi(u1.y);
            uint32_t hi, lo;
            split_pair(ac3[nt][0] * (1.f - h00 * h00),
                       ac3[nt][1] * (1.f - h01 * h01), hi, lo);
            *p0 = make_uint2(hi, lo);
            split_pair(ac3[nt][2] * (1.f - h10 * h10),
                       ac3[nt][3] * (1.f - h11 * h11), hi, lo);
            *p1 = make_uint2(hi, lo);
        }
        __syncwarp();

        // ========== GEMM4: dEdD = G1 @ W1^T (N=64, K=128) =================
        float ac4[8][4];
        #pragma unroll
        for (int nt = 0; nt < 8; nt++)
            #pragma unroll
            for (int q = 0; q < 4; q++) ac4[nt][q] = 0.f;

        #pragma unroll 1
        for (int s = 0; s < 8; s++) {
            uint2 A00 = h1p[g * 68 + 8 * s + t];
            uint2 A10 = h1p[(g + 8) * 68 + 8 * s + t];
            uint2 A01 = h1p[g * 68 + 8 * s + t + 4];
            uint2 A11 = h1p[(g + 8) * 68 + 8 * s + t + 4];
            #pragma unroll
            for (int nt = 0; nt < 8; nt++) {
                uint2 B0 = W1TB[(8 * nt + g) * 68 + 8 * s + t];
                uint2 B1 = W1TB[(8 * nt + g) * 68 + 8 * s + t + 4];
                mma16(ac4[nt], A00.x, A10.x, A01.x, A11.x, B0.x, B1.x);
                mma16(ac4[nt], A00.y, A10.y, A01.y, A11.y, B0.x, B1.x);
                mma16(ac4[nt], A00.x, A10.x, A01.x, A11.x, B0.y, B1.y);
            }
        }
        // epi4: store dEdD
        #pragma unroll
        for (int nt = 0; nt < 8; nt++) {
            int c = 8 * nt + 2 * t;
            if (ok0)
                *(float2*)(g_dEdD + (size_t)r0 * 64 + c)
                    = make_float2(ac4[nt][0], ac4[nt][1]);
            if (ok1)
                *(float2*)(g_dEdD + (size_t)r1 * 64 + c)
                    = make_float2(ac4[nt][2], ac4[nt][3]);
        }
        __syncwarp();
    }
}

// ---------------------------------------------------------------------------
// Forces: 4 pairs per warp, 8-lane groups (proven R7 config: 121.8us, 85% DRAM)
// ---------------------------------------------------------------------------
__global__ void __launch_bounds__(256)
forces_kernel(const float* __restrict__ xd, const int* __restrict__ xd_indx,
              const int* __restrict__ uj, float* __restrict__ forces, int npairs)
{
    int w    = (blockIdx.x * blockDim.x + threadIdx.x) >> 5;
    int lane = threadIdx.x & 31;
    int li   = lane & 7;
    int pr   = lane >> 3;
    int p    = 4 * w + pr;
    if (4 * w >= npairs) return;
    bool valid = (p < npairs);
    int pc = valid ? p : (npairs - 1);

    int neigh = __ldg(xd_indx + 6 * pc);
    const float4* gp = (const float4*)(g_dEdD + (size_t)neigh * 64);
    float4 ga = gp[2 * li], gb = gp[2 * li + 1];

    const float4* xr = (const float4*)(xd + (size_t)pc * 192);
    float4 a0 = __ldcs(xr + 2 * li),      b0 = __ldcs(xr + 2 * li + 1);
    float4 a1 = __ldcs(xr + 16 + 2 * li), b1 = __ldcs(xr + 17 + 2 * li);
    float4 a2 = __ldcs(xr + 32 + 2 * li), b2 = __ldcs(xr + 33 + 2 * li);

    float s0 = a0.x*ga.x + a0.y*ga.y + a0.z*ga.z + a0.w*ga.w
             + b0.x*gb.x + b0.y*gb.y + b0.z*gb.z + b0.w*gb.w;
    float s1 = a1.x*ga.x + a1.y*ga.y + a1.z*ga.z + a1.w*ga.w
             + b1.x*gb.x + b1.y*gb.y + b1.z*gb.z + b1.w*gb.w;
    float s2 = a2.x*ga.x + a2.y*ga.y + a2.z*ga.z + a2.w*ga.w
             + b2.x*gb.x + b2.y*gb.y + b2.z*gb.z + b2.w*gb.w;

    #pragma unroll
    for (int off = 4; off; off >>= 1) {
        s0 += __shfl_xor_sync(0xffffffffu, s0, off);
        s1 += __shfl_xor_sync(0xffffffffu, s1, off);
        s2 += __shfl_xor_sync(0xffffffffu, s2, off);
    }
    if (li == 0 && valid) {
        int j0 = __ldg(uj + 3 * pc);
        int j1 = __ldg(uj + 3 * pc + 1);
        int j2 = __ldg(uj + 3 * pc + 2);
        atomicAdd(&forces[3 * j0 + 0], -s0);
        atomicAdd(&forces[3 * j1 + 1], -s1);
        atomicAdd(&forces[3 * j2 + 2], -s2);
    }
}

// ---------------------------------------------------------------------------
extern "C" void kernel_launch(void* const* d_in, const int* in_sizes, int n_in,
                              void* d_out, int out_size)
{
    const float* x       = (const float*)d_in[0];
    const float* xd      = (const float*)d_in[1];
    const int*   indices = (const int*)  d_in[2];
    const int*   xd_indx = (const int*)  d_in[4];
    const int*   uj      = (const int*)  d_in[5];
    const float* W1      = (const float*)d_in[6];
    const float* b1      = (const float*)d_in[7];
    const float* W2      = (const float*)d_in[8];
    const float* b2      = (const float*)d_in[9];
    const float* W3      = (const float*)d_in[10];
    const float* b3      = (const float*)d_in[11];
    float* out = (float*)d_out;

    int natoms  = in_sizes[0] / 64;    // 50000
    int nstruct = in_sizes[3];         // 250
    int npairs  = in_sizes[5] / 3;     // 1000000

    cudaMemsetAsync(out, 0, (size_t)out_size * sizeof(float), 0);

    cudaFuncSetAttribute(mlp_kernel, cudaFuncAttributeMaxDynamicSharedMemorySize,
                         SMEM_BYTES);
    mlp_kernel<<<148, 256, SMEM_BYTES>>>(x, indices, W1, b1, W2, b2, W3, b3,
                                         out, natoms);

    int nwarps = (npairs + 3) / 4;
    int blocks = (nwarps + 7) / 8;
    forces_kernel<<<blocks, 256>>>(xd, xd_indx, uj, out + nstruct, npairs);
}